// round 1
// baseline (speedup 1.0000x reference)
#include <cuda_runtime.h>

#define NN  100000
#define NE  1600000
#define FIN 512
#define HH  128
#define CC  64

// Scratch (no runtime allocation allowed)
__device__ float g_deg[NN];                 // degree -> dinv (in place)
__device__ float g_norm[NE];                // per-edge norm
__device__ float g_h[(size_t)NN * HH];      // GEMM output / scatter source
__device__ float g_y[(size_t)NN * HH];      // scatter accumulator / GEMM input

// ---------------------------------------------------------------- norm prep
__global__ void k_deg_init() {
    int i = blockIdx.x * blockDim.x + threadIdx.x;
    if (i < NN) g_deg[i] = 1.0f;            // self-loop contributes 1
}

__global__ void k_deg_count(const int* __restrict__ dst) {
    int e = blockIdx.x * blockDim.x + threadIdx.x;
    if (e < NE) atomicAdd(&g_deg[dst[e]], 1.0f);
}

__global__ void k_dinv() {
    int i = blockIdx.x * blockDim.x + threadIdx.x;
    if (i < NN) g_deg[i] = rsqrtf(g_deg[i]);   // deg >= 1 always
}

__global__ void k_norm(const int* __restrict__ src, const int* __restrict__ dst) {
    int e = blockIdx.x * blockDim.x + threadIdx.x;
    if (e < NE) g_norm[e] = g_deg[src[e]] * g_deg[dst[e]];
}

// ------------------------------------------------- y := h * dinv^2 (self loop)
__global__ void k_init_y() {
    int i = blockIdx.x * blockDim.x + threadIdx.x;   // over NN*HH/4
    if (i < NN * (HH / 4)) {
        int node = i / (HH / 4);
        float s = g_deg[node];
        s = s * s;
        float4 v = ((const float4*)g_h)[i];
        v.x *= s; v.y *= s; v.z *= s; v.w *= s;
        ((float4*)g_y)[i] = v;
    }
}

// ------------------------------------------------- scatter: y[dst] += h[src]*norm
__global__ void k_scatter(const int* __restrict__ src, const int* __restrict__ dst) {
    int gw   = (blockIdx.x * blockDim.x + threadIdx.x) >> 5;
    int lane = threadIdx.x & 31;
    int nw   = (gridDim.x * blockDim.x) >> 5;
    for (int e = gw; e < NE; e += nw) {
        int   s = src[e];
        int   d = dst[e];
        float w = g_norm[e];
        float4 v = ((const float4*)(g_h + (size_t)s * HH))[lane];
        v.x *= w; v.y *= w; v.z *= w; v.w *= w;
        float* p = g_y + (size_t)d * HH + lane * 4;
        asm volatile("red.global.add.v4.f32 [%0], {%1,%2,%3,%4};"
                     :: "l"(p), "f"(v.x), "f"(v.y), "f"(v.z), "f"(v.w)
                     : "memory");
    }
}

// ------------------------------------------------- fp32 GEMM: C[M,128] = act(A[M,K]) @ B[K,128] + bias
// BM=128, BN=128, BK=8, 256 threads, 8x8 per thread.
template<int K, bool RIN, bool ROUT>
__global__ __launch_bounds__(256)
void k_gemm(const float* __restrict__ A, const float* __restrict__ B,
            const float* __restrict__ bias, float* __restrict__ C) {
    __shared__ float As[8][132];   // padded: conflict-free transposed stores
    __shared__ float Bs[8][128];

    int tid  = threadIdx.x;
    int row0 = blockIdx.x * 128;

    int arow = tid >> 1;           // 0..127
    int acol = (tid & 1) * 4;      // 0 or 4
    int brow = tid >> 5;           // 0..7
    int bcol = (tid & 31) * 4;

    int tx = tid & 15;             // col group
    int ty = tid >> 4;             // row group

    float acc[8][8];
#pragma unroll
    for (int i = 0; i < 8; i++)
#pragma unroll
        for (int j = 0; j < 8; j++) acc[i][j] = 0.f;

    const int rA = row0 + arow;
    for (int k0 = 0; k0 < K; k0 += 8) {
        float4 av = make_float4(0.f, 0.f, 0.f, 0.f);
        if (rA < NN) av = *(const float4*)(A + (size_t)rA * K + k0 + acol);
        if (RIN) {
            av.x = fmaxf(av.x, 0.f); av.y = fmaxf(av.y, 0.f);
            av.z = fmaxf(av.z, 0.f); av.w = fmaxf(av.w, 0.f);
        }
        As[acol + 0][arow] = av.x;
        As[acol + 1][arow] = av.y;
        As[acol + 2][arow] = av.z;
        As[acol + 3][arow] = av.w;
        *(float4*)&Bs[brow][bcol] = *(const float4*)(B + (size_t)(k0 + brow) * HH + bcol);
        __syncthreads();

#pragma unroll
        for (int k = 0; k < 8; k++) {
            float ar[8], br[8];
            *(float4*)&ar[0] = *(float4*)&As[k][ty * 8];
            *(float4*)&ar[4] = *(float4*)&As[k][ty * 8 + 4];
            *(float4*)&br[0] = *(float4*)&Bs[k][tx * 8];
            *(float4*)&br[4] = *(float4*)&Bs[k][tx * 8 + 4];
#pragma unroll
            for (int i = 0; i < 8; i++)
#pragma unroll
                for (int j = 0; j < 8; j++) acc[i][j] += ar[i] * br[j];
        }
        __syncthreads();
    }

    float bv[8];
#pragma unroll
    for (int j = 0; j < 8; j++) bv[j] = __ldg(&bias[tx * 8 + j]);

#pragma unroll
    for (int i = 0; i < 8; i++) {
        int r = row0 + ty * 8 + i;
        if (r < NN) {
            float4 o0, o1;
            float v;
            v = acc[i][0] + bv[0]; if (ROUT) v = fmaxf(v, 0.f); o0.x = v;
            v = acc[i][1] + bv[1]; if (ROUT) v = fmaxf(v, 0.f); o0.y = v;
            v = acc[i][2] + bv[2]; if (ROUT) v = fmaxf(v, 0.f); o0.z = v;
            v = acc[i][3] + bv[3]; if (ROUT) v = fmaxf(v, 0.f); o0.w = v;
            v = acc[i][4] + bv[4]; if (ROUT) v = fmaxf(v, 0.f); o1.x = v;
            v = acc[i][5] + bv[5]; if (ROUT) v = fmaxf(v, 0.f); o1.y = v;
            v = acc[i][6] + bv[6]; if (ROUT) v = fmaxf(v, 0.f); o1.z = v;
            v = acc[i][7] + bv[7]; if (ROUT) v = fmaxf(v, 0.f); o1.w = v;
            *(float4*)(C + (size_t)r * HH + tx * 8)     = o0;
            *(float4*)(C + (size_t)r * HH + tx * 8 + 4) = o1;
        }
    }
}

// ------------------------------------------------- fc3 + log_softmax (warp per node)
__global__ __launch_bounds__(256)
void k_fc3_lsm(const float* __restrict__ Y, const float* __restrict__ W,
               const float* __restrict__ b, float* __restrict__ out) {
    __shared__ float Ws[HH * CC];    // 32 KB
    __shared__ float bs[CC];
    __shared__ float ys[8][HH];

    int tid = threadIdx.x;
    for (int i = tid; i < HH * CC; i += 256) Ws[i] = W[i];
    if (tid < CC) bs[tid] = b[tid];
    __syncthreads();

    int warp = tid >> 5, lane = tid & 31;
    int node = blockIdx.x * 8 + warp;
    if (node >= NN) return;

    float4 v = ((const float4*)(Y + (size_t)node * HH))[lane];
    *(float4*)&ys[warp][lane * 4] = v;
    __syncwarp();

    float z0 = bs[lane], z1 = bs[lane + 32];
#pragma unroll 8
    for (int k = 0; k < HH; k++) {
        float yk = ys[warp][k];
        z0 += yk * Ws[k * CC + lane];
        z1 += yk * Ws[k * CC + lane + 32];
    }
    float m = fmaxf(z0, z1);
#pragma unroll
    for (int o = 16; o > 0; o >>= 1) m = fmaxf(m, __shfl_xor_sync(0xffffffffu, m, o));
    float s = expf(z0 - m) + expf(z1 - m);
#pragma unroll
    for (int o = 16; o > 0; o >>= 1) s += __shfl_xor_sync(0xffffffffu, s, o);
    float lse = m + logf(s);
    out[(size_t)node * CC + lane]      = z0 - lse;
    out[(size_t)node * CC + lane + 32] = z1 - lse;
}

// ---------------------------------------------------------------- launch
extern "C" void kernel_launch(void* const* d_in, const int* in_sizes, int n_in,
                              void* d_out, int out_size) {
    const float* x    = (const float*)d_in[0];
    const int*   ei   = (const int*)d_in[1];
    const int*   src  = ei;
    const int*   dst  = ei + NE;
    const float* W0   = (const float*)d_in[2];
    const float* b0   = (const float*)d_in[3];
    const float* W1   = (const float*)d_in[4];
    const float* b1   = (const float*)d_in[5];
    const float* W2   = (const float*)d_in[6];
    const float* b2   = (const float*)d_in[7];
    const float* f1w  = (const float*)d_in[8];
    const float* f1b  = (const float*)d_in[9];
    const float* f2w  = (const float*)d_in[10];
    const float* f2b  = (const float*)d_in[11];
    const float* f3w  = (const float*)d_in[12];
    const float* f3b  = (const float*)d_in[13];
    float* out = (float*)d_out;

    float *ph = nullptr, *py = nullptr;
    cudaGetSymbolAddress((void**)&ph, g_h);
    cudaGetSymbolAddress((void**)&py, g_y);

    const int T = 256;
    const int gN  = (NN + T - 1) / T;
    const int gE  = (NE + T - 1) / T;
    const int gG  = (NN + 127) / 128;          // 782 gemm blocks
    const int gY  = (NN * (HH / 4) + T - 1) / T;
    const int gSC = 2048;                       // scatter grid (grid-stride warps)
    const int gF  = (NN + 7) / 8;

    // normalization
    k_deg_init <<<gN, T>>>();
    k_deg_count<<<gE, T>>>(dst);
    k_dinv     <<<gN, T>>>();
    k_norm     <<<gE, T>>>(src, dst);

    // conv0: h = x @ W0 + b0 ; aggregate -> y
    k_gemm<FIN, false, false><<<gG, T>>>(x, W0, b0, ph);
    k_init_y <<<gY, T>>>();
    k_scatter<<<gSC, T>>>(src, dst);

    // conv1: h = relu(y) @ W1 + b1 ; aggregate -> y
    k_gemm<HH, true, false><<<gG, T>>>(py, W1, b1, ph);
    k_init_y <<<gY, T>>>();
    k_scatter<<<gSC, T>>>(src, dst);

    // conv2: h = relu(y) @ W2 + b2 ; aggregate -> y
    k_gemm<HH, true, false><<<gG, T>>>(py, W2, b2, ph);
    k_init_y <<<gY, T>>>();
    k_scatter<<<gSC, T>>>(src, dst);

    // fc1: h = relu(relu(y) @ fc1_w + fc1_b)
    k_gemm<HH, true, true><<<gG, T>>>(py, f1w, f1b, ph);
    // fc2: y = relu(h @ fc2_w + fc2_b)
    k_gemm<HH, false, true><<<gG, T>>>(ph, f2w, f2b, py);
    // fc3 + log_softmax
    k_fc3_lsm<<<gF, T>>>(py, f3w, f3b, out);
}

// round 3
// speedup vs baseline: 1.3837x; 1.3837x over previous
#include <cuda_runtime.h>

#define NN  100000
#define NE  1600000
#define FIN 512
#define HH  128
#define CC  64

#define SCAN_CHUNK 256
#define NBLK_SCAN  ((NN + SCAN_CHUNK - 1) / SCAN_CHUNK)   // 391

// ------------------------------------------------------------- scratch
__device__ int   g_cnt[NN];                  // in-degree (excl self loop)
__device__ float g_deg[NN];                  // dinv
__device__ int   g_rs[NN + 1];               // CSR row_start (by dst)
__device__ int   g_cur[NN];                  // fill cursors
__device__ int   g_part[NBLK_SCAN];          // scan partials
__device__ int2  g_epk[NE];                  // packed (src, norm-bits) sorted by dst
__device__ float g_h[(size_t)NN * HH];       // GEMM output / pull source
__device__ float g_y[(size_t)NN * HH];       // pull output / GEMM input

// ------------------------------------------------------------- degree / dinv
__global__ void k_zero_cnt() {
    int i = blockIdx.x * blockDim.x + threadIdx.x;
    if (i < NN) g_cnt[i] = 0;
}

__global__ void k_count(const int* __restrict__ dst) {
    int e = blockIdx.x * blockDim.x + threadIdx.x;
    if (e < NE) atomicAdd(&g_cnt[dst[e]], 1);
}

__global__ void k_dinv() {
    int i = blockIdx.x * blockDim.x + threadIdx.x;
    if (i < NN) g_deg[i] = rsqrtf((float)g_cnt[i] + 1.0f);  // +1 self loop
}

// ------------------------------------------------------------- 3-kernel exclusive scan of g_cnt
__global__ __launch_bounds__(SCAN_CHUNK) void k_scan1() {
    __shared__ int sm[SCAN_CHUNK];
    int i = blockIdx.x * SCAN_CHUNK + threadIdx.x;
    int v = (i < NN) ? g_cnt[i] : 0;
    sm[threadIdx.x] = v;
    __syncthreads();
    // Hillis-Steele inclusive scan
    for (int o = 1; o < SCAN_CHUNK; o <<= 1) {
        int t = (threadIdx.x >= o) ? sm[threadIdx.x - o] : 0;
        __syncthreads();
        sm[threadIdx.x] += t;
        __syncthreads();
    }
    if (i < NN) g_rs[i] = sm[threadIdx.x] - v;          // exclusive, chunk-local
    if (threadIdx.x == SCAN_CHUNK - 1) g_part[blockIdx.x] = sm[threadIdx.x];
}

__global__ __launch_bounds__(512) void k_scan2() {      // single block
    __shared__ int sm[512];
    int v = (threadIdx.x < NBLK_SCAN) ? g_part[threadIdx.x] : 0;
    sm[threadIdx.x] = v;
    __syncthreads();
    for (int o = 1; o < 512; o <<= 1) {
        int t = (threadIdx.x >= o) ? sm[threadIdx.x - o] : 0;
        __syncthreads();
        sm[threadIdx.x] += t;
        __syncthreads();
    }
    if (threadIdx.x < NBLK_SCAN) g_part[threadIdx.x] = sm[threadIdx.x] - v;  // exclusive
}

__global__ void k_scan3() {
    int i = blockIdx.x * blockDim.x + threadIdx.x;
    if (i < NN) {
        int v = g_rs[i] + g_part[i >> 8];   // SCAN_CHUNK == 256
        g_rs[i]  = v;
        g_cur[i] = v;
    }
    if (i == 0) g_rs[NN] = NE;
}

// ------------------------------------------------------------- CSR fill (with edge norm)
__global__ void k_fill(const int* __restrict__ src, const int* __restrict__ dst) {
    int e = blockIdx.x * blockDim.x + threadIdx.x;
    if (e < NE) {
        int s = src[e], d = dst[e];
        float w = g_deg[s] * g_deg[d];
        int pos = atomicAdd(&g_cur[d], 1);
        g_epk[pos] = make_int2(s, __float_as_int(w));
    }
}

// ------------------------------------------------------------- pull aggregation (warp per dst)
// y[node] = dinv[node]^2 * h[node] + sum_in_edges w_e * h[src_e]
__global__ __launch_bounds__(256) void k_pull() {
    int node = (blockIdx.x * blockDim.x + threadIdx.x) >> 5;
    int lane = threadIdx.x & 31;
    if (node >= NN) return;

    const float4* hp = (const float4*)g_h;
    float s = g_deg[node];
    float ss = s * s;
    float4 acc = hp[(size_t)node * 32 + lane];
    acc.x *= ss; acc.y *= ss; acc.z *= ss; acc.w *= ss;

    int e   = g_rs[node];
    int end = g_rs[node + 1];
    for (; e + 2 <= end; e += 2) {
        int2 p0 = g_epk[e];
        int2 p1 = g_epk[e + 1];
        float4 v0 = hp[(size_t)p0.x * 32 + lane];
        float4 v1 = hp[(size_t)p1.x * 32 + lane];
        float w0 = __int_as_float(p0.y);
        float w1 = __int_as_float(p1.y);
        acc.x += w0 * v0.x; acc.y += w0 * v0.y; acc.z += w0 * v0.z; acc.w += w0 * v0.w;
        acc.x += w1 * v1.x; acc.y += w1 * v1.y; acc.z += w1 * v1.z; acc.w += w1 * v1.w;
    }
    if (e < end) {
        int2 p0 = g_epk[e];
        float4 v0 = hp[(size_t)p0.x * 32 + lane];
        float w0 = __int_as_float(p0.y);
        acc.x += w0 * v0.x; acc.y += w0 * v0.y; acc.z += w0 * v0.z; acc.w += w0 * v0.w;
    }
    ((float4*)g_y)[(size_t)node * 32 + lane] = acc;
}

// ------------------------------------------------------------- fp32 GEMM: C[M,128] = act(A[M,K]) @ B[K,128] + bias
// BM=128, BN=128, BK=16, 256 threads, 8x8 per thread.
template<int K, bool RIN, bool ROUT>
__global__ __launch_bounds__(256)
void k_gemm(const float* __restrict__ A, const float* __restrict__ B,
            const float* __restrict__ bias, float* __restrict__ C) {
    __shared__ float As[16][132];
    __shared__ float Bs[16][128];

    int tid  = threadIdx.x;
    int row0 = blockIdx.x * 128;

    int tx = tid & 15;             // col group
    int ty = tid >> 4;             // row group

    float acc[8][8];
#pragma unroll
    for (int i = 0; i < 8; i++)
#pragma unroll
        for (int j = 0; j < 8; j++) acc[i][j] = 0.f;

    for (int k0 = 0; k0 < K; k0 += 16) {
        // A: 128 rows x 16 cols = 512 float4, 2 per thread
#pragma unroll
        for (int j = 0; j < 2; j++) {
            int idx  = tid + j * 256;
            int arow = idx >> 2;            // 0..127
            int acol = (idx & 3) * 4;       // 0,4,8,12
            int rA   = row0 + arow;
            float4 av = make_float4(0.f, 0.f, 0.f, 0.f);
            if (rA < NN) av = *(const float4*)(A + (size_t)rA * K + k0 + acol);
            if (RIN) {
                av.x = fmaxf(av.x, 0.f); av.y = fmaxf(av.y, 0.f);
                av.z = fmaxf(av.z, 0.f); av.w = fmaxf(av.w, 0.f);
            }
            As[acol + 0][arow] = av.x;
            As[acol + 1][arow] = av.y;
            As[acol + 2][arow] = av.z;
            As[acol + 3][arow] = av.w;
        }
        // B: 16 rows x 128 cols = 512 float4, 2 per thread
#pragma unroll
        for (int j = 0; j < 2; j++) {
            int idx  = tid + j * 256;
            int brow = idx >> 5;            // 0..15
            int bcol = (idx & 31) * 4;
            *(float4*)&Bs[brow][bcol] = *(const float4*)(B + (size_t)(k0 + brow) * HH + bcol);
        }
        __syncthreads();

#pragma unroll
        for (int k = 0; k < 16; k++) {
            float ar[8], br[8];
            *(float4*)&ar[0] = *(float4*)&As[k][ty * 8];
            *(float4*)&ar[4] = *(float4*)&As[k][ty * 8 + 4];
            *(float4*)&br[0] = *(float4*)&Bs[k][tx * 8];
            *(float4*)&br[4] = *(float4*)&Bs[k][tx * 8 + 4];
#pragma unroll
            for (int i = 0; i < 8; i++)
#pragma unroll
                for (int j = 0; j < 8; j++) acc[i][j] += ar[i] * br[j];
        }
        __syncthreads();
    }

    float bv[8];
#pragma unroll
    for (int j = 0; j < 8; j++) bv[j] = __ldg(&bias[tx * 8 + j]);

#pragma unroll
    for (int i = 0; i < 8; i++) {
        int r = row0 + ty * 8 + i;
        if (r < NN) {
            float4 o0, o1;
            float v;
            v = acc[i][0] + bv[0]; if (ROUT) v = fmaxf(v, 0.f); o0.x = v;
            v = acc[i][1] + bv[1]; if (ROUT) v = fmaxf(v, 0.f); o0.y = v;
            v = acc[i][2] + bv[2]; if (ROUT) v = fmaxf(v, 0.f); o0.z = v;
            v = acc[i][3] + bv[3]; if (ROUT) v = fmaxf(v, 0.f); o0.w = v;
            v = acc[i][4] + bv[4]; if (ROUT) v = fmaxf(v, 0.f); o1.x = v;
            v = acc[i][5] + bv[5]; if (ROUT) v = fmaxf(v, 0.f); o1.y = v;
            v = acc[i][6] + bv[6]; if (ROUT) v = fmaxf(v, 0.f); o1.z = v;
            v = acc[i][7] + bv[7]; if (ROUT) v = fmaxf(v, 0.f); o1.w = v;
            *(float4*)(C + (size_t)r * HH + tx * 8)     = o0;
            *(float4*)(C + (size_t)r * HH + tx * 8 + 4) = o1;
        }
    }
}

// ------------------------------------------------------------- fc3 + log_softmax (warp per node)
__global__ __launch_bounds__(256)
void k_fc3_lsm(const float* __restrict__ Y, const float* __restrict__ W,
               const float* __restrict__ b, float* __restrict__ out) {
    __shared__ float Ws[HH * CC];
    __shared__ float bs[CC];
    __shared__ float ys[8][HH];

    int tid = threadIdx.x;
    for (int i = tid; i < HH * CC; i += 256) Ws[i] = W[i];
    if (tid < CC) bs[tid] = b[tid];
    __syncthreads();

    int warp = tid >> 5, lane = tid & 31;
    int node = blockIdx.x * 8 + warp;
    if (node >= NN) return;

    float4 v = ((const float4*)(Y + (size_t)node * HH))[lane];
    *(float4*)&ys[warp][lane * 4] = v;
    __syncwarp();

    float z0 = bs[lane], z1 = bs[lane + 32];
#pragma unroll 8
    for (int k = 0; k < HH; k++) {
        float yk = ys[warp][k];
        z0 += yk * Ws[k * CC + lane];
        z1 += yk * Ws[k * CC + lane + 32];
    }
    float m = fmaxf(z0, z1);
#pragma unroll
    for (int o = 16; o > 0; o >>= 1) m = fmaxf(m, __shfl_xor_sync(0xffffffffu, m, o));
    float s = expf(z0 - m) + expf(z1 - m);
#pragma unroll
    for (int o = 16; o > 0; o >>= 1) s += __shfl_xor_sync(0xffffffffu, s, o);
    float lse = m + logf(s);
    out[(size_t)node * CC + lane]      = z0 - lse;
    out[(size_t)node * CC + lane + 32] = z1 - lse;
}

// ------------------------------------------------------------- launch
extern "C" void kernel_launch(void* const* d_in, const int* in_sizes, int n_in,
                              void* d_out, int out_size) {
    const float* x    = (const float*)d_in[0];
    const int*   ei   = (const int*)d_in[1];
    const int*   src  = ei;
    const int*   dst  = ei + NE;
    const float* W0   = (const float*)d_in[2];
    const float* b0   = (const float*)d_in[3];
    const float* W1   = (const float*)d_in[4];
    const float* b1   = (const float*)d_in[5];
    const float* W2   = (const float*)d_in[6];
    const float* b2   = (const float*)d_in[7];
    const float* f1w  = (const float*)d_in[8];
    const float* f1b  = (const float*)d_in[9];
    const float* f2w  = (const float*)d_in[10];
    const float* f2b  = (const float*)d_in[11];
    const float* f3w  = (const float*)d_in[12];
    const float* f3b  = (const float*)d_in[13];
    float* out = (float*)d_out;

    float *ph = nullptr, *py = nullptr;
    cudaGetSymbolAddress((void**)&ph, g_h);
    cudaGetSymbolAddress((void**)&py, g_y);

    const int T  = 256;
    const int gN = (NN + T - 1) / T;
    const int gE = (NE + T - 1) / T;
    const int gG = (NN + 127) / 128;
    const int gP = (NN * 32 + T - 1) / T;   // warp per node
    const int gF = (NN + 7) / 8;

    // degree + dinv (launches 0..2)
    k_zero_cnt<<<gN, T>>>();
    k_count   <<<gE, T>>>(dst);
    k_dinv    <<<gN, T>>>();

    // conv0 GEMM early (launch 3 — ncu capture slot)
    k_gemm<FIN, false, false><<<gG, T>>>(x, W0, b0, ph);

    // CSR build (independent of gemm0)
    k_scan1<<<NBLK_SCAN, SCAN_CHUNK>>>();
    k_scan2<<<1, 512>>>();
    k_scan3<<<gN, T>>>();
    k_fill <<<gE, T>>>(src, dst);

    // conv0 aggregate
    k_pull<<<gP, T>>>();

    // conv1
    k_gemm<HH, true, false><<<gG, T>>>(py, W1, b1, ph);
    k_pull<<<gP, T>>>();

    // conv2
    k_gemm<HH, true, false><<<gG, T>>>(py, W2, b2, ph);
    k_pull<<<gP, T>>>();

    // MLP head
    k_gemm<HH, true, true ><<<gG, T>>>(py, f1w, f1b, ph);
    k_gemm<HH, false, true><<<gG, T>>>(ph, f2w, f2b, py);
    k_fc3_lsm<<<gF, T>>>(py, f3w, f3b, out);
}

// round 5
// speedup vs baseline: 1.4666x; 1.0599x over previous
#include <cuda_runtime.h>
#include <cstdint>

#define NN  100000
#define NE  1600000
#define FIN 512
#define HH  128
#define CC  64

#define SCAN_CHUNK 256
#define NBLK_SCAN  ((NN + SCAN_CHUNK - 1) / SCAN_CHUNK)   // 391

// ------------------------------------------------------------- scratch
__device__ int    g_cnt[NN];
__device__ float  g_deg[NN];
__device__ int    g_rs[NN + 1];
__device__ int    g_cur[NN];
__device__ int    g_part[NBLK_SCAN];
__device__ int2   g_epk[NE];
__device__ float  g_h[(size_t)NN * HH];
__device__ float  g_y[(size_t)NN * HH];
// packed weight fragments: [k8block][n(128)][c(4)] float4 = (hi_k, hi_k+4, lo_k, lo_k+4)
__device__ float4 g_wpk[(FIN / 8) * 128 * 4];   // max K=512 -> 32768 float4

// ============================================================= helpers
__device__ __forceinline__ uint32_t smem_u32(const void* p) {
    uint32_t a;
    asm("{ .reg .u64 t; cvta.to.shared.u64 t, %1; cvt.u32.u64 %0, t; }" : "=r"(a) : "l"(p));
    return a;
}
__device__ __forceinline__ uint32_t tf32_hi(float x) {
    uint32_t u;
    asm("cvt.rna.tf32.f32 %0, %1;" : "=r"(u) : "f"(x));
    return u;
}
__device__ __forceinline__ void mma_tf32(float* d, const uint32_t* a, uint32_t b0, uint32_t b1) {
    asm volatile(
        "mma.sync.aligned.m16n8k8.row.col.f32.tf32.tf32.f32 "
        "{%0,%1,%2,%3}, {%4,%5,%6,%7}, {%8,%9}, {%0,%1,%2,%3};"
        : "+f"(d[0]), "+f"(d[1]), "+f"(d[2]), "+f"(d[3])
        : "r"(a[0]), "r"(a[1]), "r"(a[2]), "r"(a[3]), "r"(b0), "r"(b1));
}
__device__ __forceinline__ uint4 lds128(uint32_t addr) {
    uint4 v;
    asm volatile("ld.shared.v4.b32 {%0,%1,%2,%3}, [%4];"
                 : "=r"(v.x), "=r"(v.y), "=r"(v.z), "=r"(v.w) : "r"(addr));
    return v;
}
__device__ __forceinline__ void sts128(uint32_t addr, uint32_t a, uint32_t b, uint32_t c, uint32_t d) {
    asm volatile("st.shared.v4.b32 [%0], {%1,%2,%3,%4};"
                 :: "r"(addr), "r"(a), "r"(b), "r"(c), "r"(d));
}
__device__ __forceinline__ void cp_async16(uint32_t sdst, const void* gsrc) {
    asm volatile("cp.async.ca.shared.global [%0], [%1], 16;" :: "r"(sdst), "l"(gsrc));
}
#define CP_COMMIT() asm volatile("cp.async.commit_group;" ::: "memory")
#define CP_WAIT(n)  asm volatile("cp.async.wait_group %0;" :: "n"(n) : "memory")

// ============================================================= small kernels
__global__ void k_zero_cnt() {
    int i = blockIdx.x * blockDim.x + threadIdx.x;
    if (i < NN) g_cnt[i] = 0;
}
__global__ void k_count(const int* __restrict__ dst) {
    int e = blockIdx.x * blockDim.x + threadIdx.x;
    if (e < NE) atomicAdd(&g_cnt[dst[e]], 1);
}
__global__ void k_dinv() {
    int i = blockIdx.x * blockDim.x + threadIdx.x;
    if (i < NN) g_deg[i] = rsqrtf((float)g_cnt[i] + 1.0f);
}
__global__ __launch_bounds__(SCAN_CHUNK) void k_scan1() {
    __shared__ int sm[SCAN_CHUNK];
    int i = blockIdx.x * SCAN_CHUNK + threadIdx.x;
    int v = (i < NN) ? g_cnt[i] : 0;
    sm[threadIdx.x] = v;
    __syncthreads();
    for (int o = 1; o < SCAN_CHUNK; o <<= 1) {
        int t = (threadIdx.x >= o) ? sm[threadIdx.x - o] : 0;
        __syncthreads();
        sm[threadIdx.x] += t;
        __syncthreads();
    }
    if (i < NN) g_rs[i] = sm[threadIdx.x] - v;
    if (threadIdx.x == SCAN_CHUNK - 1) g_part[blockIdx.x] = sm[threadIdx.x];
}
__global__ __launch_bounds__(512) void k_scan2() {
    __shared__ int sm[512];
    int v = (threadIdx.x < NBLK_SCAN) ? g_part[threadIdx.x] : 0;
    sm[threadIdx.x] = v;
    __syncthreads();
    for (int o = 1; o < 512; o <<= 1) {
        int t = (threadIdx.x >= o) ? sm[threadIdx.x - o] : 0;
        __syncthreads();
        sm[threadIdx.x] += t;
        __syncthreads();
    }
    if (threadIdx.x < NBLK_SCAN) g_part[threadIdx.x] = sm[threadIdx.x] - v;
}
__global__ void k_scan3() {
    int i = blockIdx.x * blockDim.x + threadIdx.x;
    if (i < NN) {
        int v = g_rs[i] + g_part[i >> 8];
        g_rs[i]  = v;
        g_cur[i] = v;
    }
    if (i == 0) g_rs[NN] = NE;
}
__global__ void k_fill(const int* __restrict__ src, const int* __restrict__ dst) {
    int e = blockIdx.x * blockDim.x + threadIdx.x;
    if (e < NE) {
        int s = src[e], d = dst[e];
        float w = g_deg[s] * g_deg[d];
        int pos = atomicAdd(&g_cur[d], 1);
        g_epk[pos] = make_int2(s, __float_as_int(w));
    }
}

// W[K,128] -> packed fragment layout g_wpk[b][n][c] = (hi W[8b+c][n], hi W[8b+c+4][n], lo.., lo..)
template<int K>
__global__ void k_wconv(const float* __restrict__ W) {
    int idx = blockIdx.x * blockDim.x + threadIdx.x;   // (b*128+n)*4+c
    if (idx < (K / 8) * 128 * 4) {
        int c = idx & 3;
        int n = (idx >> 2) & 127;
        int b = idx >> 9;
        float w0 = W[(8 * b + c) * 128 + n];
        float w1 = W[(8 * b + c + 4) * 128 + n];
        uint32_t h0 = tf32_hi(w0), h1 = tf32_hi(w1);
        uint32_t l0 = tf32_hi(w0 - __uint_as_float(h0));
        uint32_t l1 = tf32_hi(w1 - __uint_as_float(h1));
        g_wpk[idx] = make_float4(__uint_as_float(h0), __uint_as_float(h1),
                                 __uint_as_float(l0), __uint_as_float(l1));
    }
}

// ------------------------------------------------------------- pull aggregation
__global__ __launch_bounds__(256) void k_pull() {
    int node = (blockIdx.x * blockDim.x + threadIdx.x) >> 5;
    int lane = threadIdx.x & 31;
    if (node >= NN) return;

    const float4* hp = (const float4*)g_h;
    float s = g_deg[node];
    float ss = s * s;
    float4 acc = hp[(size_t)node * 32 + lane];
    acc.x *= ss; acc.y *= ss; acc.z *= ss; acc.w *= ss;

    int e   = g_rs[node];
    int end = g_rs[node + 1];
    for (; e + 2 <= end; e += 2) {
        int2 p0 = g_epk[e];
        int2 p1 = g_epk[e + 1];
        float4 v0 = hp[(size_t)p0.x * 32 + lane];
        float4 v1 = hp[(size_t)p1.x * 32 + lane];
        float w0 = __int_as_float(p0.y);
        float w1 = __int_as_float(p1.y);
        acc.x += w0 * v0.x; acc.y += w0 * v0.y; acc.z += w0 * v0.z; acc.w += w0 * v0.w;
        acc.x += w1 * v1.x; acc.y += w1 * v1.y; acc.z += w1 * v1.z; acc.w += w1 * v1.w;
    }
    if (e < end) {
        int2 p0 = g_epk[e];
        float4 v0 = hp[(size_t)p0.x * 32 + lane];
        float w0 = __int_as_float(p0.y);
        acc.x += w0 * v0.x; acc.y += w0 * v0.y; acc.z += w0 * v0.z; acc.w += w0 * v0.w;
    }
    ((float4*)g_y)[(size_t)node * 32 + lane] = acc;
}

// ============================================================= mma.sync 3xTF32 GEMM
// C[M,128] = act(A[M,K]) @ W + bias   (W pre-packed in g_wpk)
// CTA 128x128, K-slab 16, double-buffered. 8 warps, each 32 rows x 64 cols.
// smem stage: A[bb][r][c] float4 (16KB) + B[bb][n][c] float4 (16KB); stage stride 32KB.
#define STG_STRIDE 32768
#define SMEM_MM    65536

template<int K, bool RIN, bool ROUT>
__global__ __launch_bounds__(256)
void k_gemm_mm(const float* __restrict__ A, const float* __restrict__ bias,
               float* __restrict__ C) {
    extern __shared__ char smem[];
    constexpr int NS = K / 16;
    uint32_t sb = smem_u32(smem);

    int tid  = threadIdx.x;
    int w    = tid >> 5;
    int lane = tid & 31;
    int row0 = blockIdx.x * 128;

    int roww = (w & 3) * 32;       // warp row offset
    int colw = (w >> 2) * 64;      // warp col offset

    // A staging: thread -> (r = tid>>1, half = tid&1) covers (row, 8 k)
    int r    = tid >> 1;
    int half = tid & 1;
    int grow = row0 + r;
    bool rok = grow < NN;
    const float* ap = A + (size_t)grow * K + half * 8;

    float4 v0, v1;
    auto loadA = [&](int s) {
        if (rok) {
            v0 = *(const float4*)(ap + s * 16);
            v1 = *(const float4*)(ap + s * 16 + 4);
        } else {
            v0 = make_float4(0.f, 0.f, 0.f, 0.f);
            v1 = make_float4(0.f, 0.f, 0.f, 0.f);
        }
    };
    auto cpB = [&](int s) {
        uint32_t sdst = sb + (uint32_t)((s & 1) * STG_STRIDE + 16384);
        const float4* gsrc = g_wpk + s * 1024;
#pragma unroll
        for (int j = 0; j < 4; j++)
            cp_async16(sdst + (tid + j * 256) * 16, gsrc + tid + j * 256);
        CP_COMMIT();
    };
    auto stsA = [&](int buf) {
        float hx[4], lx[4], hy[4], ly[4];
        const float* p0 = &v0.x;
        const float* p1 = &v1.x;
#pragma unroll
        for (int c = 0; c < 4; c++) {
            float a0 = p0[c], a1 = p1[c];
            if (RIN) { a0 = fmaxf(a0, 0.f); a1 = fmaxf(a1, 0.f); }
            uint32_t h0 = tf32_hi(a0), h1 = tf32_hi(a1);
            hx[c] = __uint_as_float(h0);
            hy[c] = __uint_as_float(h1);
            lx[c] = __uint_as_float(tf32_hi(a0 - hx[c]));
            ly[c] = __uint_as_float(tf32_hi(a1 - hy[c]));
        }
        uint32_t base = sb + (uint32_t)(buf * STG_STRIDE + half * 8192 + r * 64);
#pragma unroll
        for (int c = 0; c < 4; c++)
            sts128(base + c * 16, __float_as_uint(hx[c]), __float_as_uint(hy[c]),
                   __float_as_uint(lx[c]), __float_as_uint(ly[c]));
    };

    float acc[2][8][4];
#pragma unroll
    for (int rb = 0; rb < 2; rb++)
#pragma unroll
        for (int nb = 0; nb < 8; nb++)
#pragma unroll
            for (int c = 0; c < 4; c++) acc[rb][nb][c] = 0.f;

    loadA(0);
    cpB(0);

    for (int s = 0; s < NS; s++) {
        int buf = s & 1;
        stsA(buf);
        if (s + 1 < NS) {
            loadA(s + 1);
            cpB(s + 1);
            CP_WAIT(1);
        } else {
            CP_WAIT(0);
        }
        __syncthreads();

        uint32_t abase = sb + (uint32_t)(buf * STG_STRIDE);
        uint32_t bbase = abase + 16384;
        int g4 = lane >> 2, l4 = lane & 3;
#pragma unroll
        for (int bb = 0; bb < 2; bb++) {
            uint32_t ab = abase + bb * 8192;
            uint32_t bbs = bbase + bb * 8192;
            uint32_t ahi[2][4], alo[2][4];
#pragma unroll
            for (int rb = 0; rb < 2; rb++) {
                uint4 q  = lds128(ab + (uint32_t)((roww + rb * 16 + g4) * 64 + l4 * 16));
                uint4 q2 = lds128(ab + (uint32_t)((roww + rb * 16 + 8 + g4) * 64 + l4 * 16));
                ahi[rb][0] = q.x;  ahi[rb][1] = q2.x; ahi[rb][2] = q.y;  ahi[rb][3] = q2.y;
                alo[rb][0] = q.z;  alo[rb][1] = q2.z; alo[rb][2] = q.w;  alo[rb][3] = q2.w;
            }
#pragma unroll
            for (int nb = 0; nb < 8; nb++) {
                uint4 f = lds128(bbs + (uint32_t)((colw + nb * 8 + g4) * 64 + l4 * 16));
#pragma unroll
                for (int rb = 0; rb < 2; rb++) {
                    mma_tf32(acc[rb][nb], ahi[rb], f.x, f.y);
                    mma_tf32(acc[rb][nb], ahi[rb], f.z, f.w);
                    mma_tf32(acc[rb][nb], alo[rb], f.x, f.y);
                }
            }
        }
        __syncthreads();
    }

    // epilogue
    int g4 = lane >> 2, l4 = lane & 3;
#pragma unroll
    for (int nb = 0; nb < 8; nb++) {
        int col = colw + nb * 8 + l4 * 2;
        float b0 = __ldg(bias + col);
        float b1 = __ldg(bias + col + 1);
#pragma unroll
        for (int rb = 0; rb < 2; rb++) {
            int rg = row0 + roww + rb * 16 + g4;
            if (rg < NN) {
                float o0 = acc[rb][nb][0] + b0;
                float o1 = acc[rb][nb][1] + b1;
                if (ROUT) { o0 = fmaxf(o0, 0.f); o1 = fmaxf(o1, 0.f); }
                *(float2*)(C + (size_t)rg * 128 + col) = make_float2(o0, o1);
            }
            if (rg + 8 < NN) {
                float o2 = acc[rb][nb][2] + b0;
                float o3 = acc[rb][nb][3] + b1;
                if (ROUT) { o2 = fmaxf(o2, 0.f); o3 = fmaxf(o3, 0.f); }
                *(float2*)(C + (size_t)(rg + 8) * 128 + col) = make_float2(o2, o3);
            }
        }
    }
}

// ------------------------------------------------------------- fc3 + log_softmax
__global__ __launch_bounds__(256)
void k_fc3_lsm(const float* __restrict__ Y, const float* __restrict__ W,
               const float* __restrict__ b, float* __restrict__ out) {
    __shared__ float Ws[HH * CC];
    __shared__ float bs[CC];
    __shared__ float ys[8][HH];

    int tid = threadIdx.x;
    for (int i = tid; i < HH * CC; i += 256) Ws[i] = W[i];
    if (tid < CC) bs[tid] = b[tid];
    __syncthreads();

    int warp = tid >> 5, lane = tid & 31;
    int node = blockIdx.x * 8 + warp;
    if (node >= NN) return;

    float4 v = ((const float4*)(Y + (size_t)node * HH))[lane];
    *(float4*)&ys[warp][lane * 4] = v;
    __syncwarp();

    float z0 = bs[lane], z1 = bs[lane + 32];
#pragma unroll 8
    for (int k = 0; k < HH; k++) {
        float yk = ys[warp][k];
        z0 += yk * Ws[k * CC + lane];
        z1 += yk * Ws[k * CC + lane + 32];
    }
    float m = fmaxf(z0, z1);
#pragma unroll
    for (int o = 16; o > 0; o >>= 1) m = fmaxf(m, __shfl_xor_sync(0xffffffffu, m, o));
    float s = expf(z0 - m) + expf(z1 - m);
#pragma unroll
    for (int o = 16; o > 0; o >>= 1) s += __shfl_xor_sync(0xffffffffu, s, o);
    float lse = m + logf(s);
    out[(size_t)node * CC + lane]      = z0 - lse;
    out[(size_t)node * CC + lane + 32] = z1 - lse;
}

// ============================================================= launch
extern "C" void kernel_launch(void* const* d_in, const int* in_sizes, int n_in,
                              void* d_out, int out_size) {
    const float* x    = (const float*)d_in[0];
    const int*   ei   = (const int*)d_in[1];
    const int*   src  = ei;
    const int*   dst  = ei + NE;
    const float* W0   = (const float*)d_in[2];
    const float* b0   = (const float*)d_in[3];
    const float* W1   = (const float*)d_in[4];
    const float* b1   = (const float*)d_in[5];
    const float* W2   = (const float*)d_in[6];
    const float* b2   = (const float*)d_in[7];
    const float* f1w  = (const float*)d_in[8];
    const float* f1b  = (const float*)d_in[9];
    const float* f2w  = (const float*)d_in[10];
    const float* f2b  = (const float*)d_in[11];
    const float* f3w  = (const float*)d_in[12];
    const float* f3b  = (const float*)d_in[13];
    float* out = (float*)d_out;

    float *ph = nullptr, *py = nullptr;
    cudaGetSymbolAddress((void**)&ph, g_h);
    cudaGetSymbolAddress((void**)&py, g_y);

    cudaFuncSetAttribute(k_gemm_mm<FIN, false, false>, cudaFuncAttributeMaxDynamicSharedMemorySize, SMEM_MM);
    cudaFuncSetAttribute(k_gemm_mm<HH,  true,  false>, cudaFuncAttributeMaxDynamicSharedMemorySize, SMEM_MM);
    cudaFuncSetAttribute(k_gemm_mm<HH,  true,  true >, cudaFuncAttributeMaxDynamicSharedMemorySize, SMEM_MM);
    cudaFuncSetAttribute(k_gemm_mm<HH,  false, true >, cudaFuncAttributeMaxDynamicSharedMemorySize, SMEM_MM);

    const int T  = 256;
    const int gN = (NN + T - 1) / T;
    const int gE = (NE + T - 1) / T;
    const int gG = (NN + 127) / 128;
    const int gP = (NN * 32 + T - 1) / T;
    const int gF = (NN + 7) / 8;
    const int gW512 = ((FIN / 8) * 512 + T - 1) / T;
    const int gW128 = ((HH  / 8) * 512 + T - 1) / T;

    k_zero_cnt<<<gN, T>>>();
    k_count   <<<gE, T>>>(dst);
    k_dinv    <<<gN, T>>>();
    k_scan1   <<<NBLK_SCAN, SCAN_CHUNK>>>();
    k_wconv<FIN><<<gW512, T>>>(W0);
    // launch #6: ncu capture slot
    k_gemm_mm<FIN, false, false><<<gG, T, SMEM_MM>>>(x, b0, ph);
    // CSR build
    k_scan2<<<1, 512>>>();
    k_scan3<<<gN, T>>>();
    k_fill <<<gE, T>>>(src, dst);
    // conv0 aggregate
    k_pull<<<gP, T>>>();
    // conv1
    k_wconv<HH><<<gW128, T>>>(W1);
    k_gemm_mm<HH, true, false><<<gG, T, SMEM_MM>>>(py, b1, ph);
    k_pull<<<gP, T>>>();
    // conv2
    k_wconv<HH><<<gW128, T>>>(W2);
    k_gemm_mm<HH, true, false><<<gG, T, SMEM_MM>>>(py, b2, ph);
    k_pull<<<gP, T>>>();
    // MLP head
    k_wconv<HH><<<gW128, T>>>(f1w);
    k_gemm_mm<HH, true, true ><<<gG, T, SMEM_MM>>>(py, f1b, ph);
    k_wconv<HH><<<gW128, T>>>(f2w);
    k_gemm_mm<HH, false, true><<<gG, T, SMEM_MM>>>(ph, f2b, py);
    k_fc3_lsm<<<gF, T>>>(py, f3w, f3b, out);
}